// round 14
// baseline (speedup 1.0000x reference)
#include <cuda_runtime.h>
#include <math.h>
#include <stdint.h>

#define NUM_LEVEL 16
#define N_POINTS  262144
#define N_DENSE   5            // levels 0..4 are dense for these params
#define N_HASH    11           // levels 5..15 hashed, hsize = 2^19
#define HASH_MASK 0x7FFFFu     // 2^19 - 1

struct DenseMeta {
    float    scale;
    uint32_t res;
    uint32_t offset;
    uint32_t pad;
};
struct HashMeta {
    float    scale;
    uint32_t offset;
};

struct MetaD { DenseMeta lv[N_DENSE]; };
struct MetaH { HashMeta  lv[N_HASH];  };

// ---------------- Dense kernel: levels 0..4, pure grid indexing ----------------
__global__ void __launch_bounds__(256)
grid_encode_dense(const float* __restrict__ pts,
                  const float2* __restrict__ emb,
                  float2* __restrict__ out,
                  MetaD meta)
{
    const uint32_t tid = blockIdx.x * blockDim.x + threadIdx.x;
    if (tid >= (uint32_t)N_POINTS * N_DENSE) return;

    const uint32_t n = tid / N_DENSE;       // constant div -> mulhi
    const uint32_t l = tid - n * N_DENSE;   // 0..4

    const float inx = __ldg(pts + n * 3 + 0);
    const float iny = __ldg(pts + n * 3 + 1);
    const float inz = __ldg(pts + n * 3 + 2);

    const DenseMeta m = meta.lv[l];

    const float px = (inx + 1.0f) * 0.5f * m.scale;
    const float py = (iny + 1.0f) * 0.5f * m.scale;
    const float pz = (inz + 1.0f) * 0.5f * m.scale;

    const float gx = floorf(px), gy = floorf(py), gz = floorf(pz);
    const float fx = px - gx,   fy = py - gy,   fz = pz - gz;

    const uint32_t ix = (uint32_t)gx;
    const uint32_t iy = (uint32_t)gy;
    const uint32_t iz = (uint32_t)gz;

    const float wx[2] = {1.0f - fx, fx};
    const float wy[2] = {1.0f - fy, fy};
    const float wz[2] = {1.0f - fz, fz};

    const float2* __restrict__ table = emb + m.offset;
    const uint32_t r  = m.res;
    const uint32_t r2 = r * r;
    const uint32_t base = ix + iy * r + iz * r2;

    float accx = 0.0f, accy = 0.0f;

    #pragma unroll
    for (int c = 0; c < 8; ++c) {
        const uint32_t bx = (uint32_t)(c & 1);
        const uint32_t by = (uint32_t)((c >> 1) & 1);
        const uint32_t bz = (uint32_t)(c >> 2);
        const uint32_t idx = base + bx + by * r + bz * r2;

        const float w = wx[bx] * wy[by] * wz[bz];
        const float2 f = __ldg(table + idx);
        accx = fmaf(w, f.x, accx);
        accy = fmaf(w, f.y, accy);
    }

    __stcs(out + n * (uint32_t)NUM_LEVEL + l, make_float2(accx, accy));
}

// ---------------- Hash kernel: levels 5..15, pure hash indexing ----------------
__global__ void __launch_bounds__(256)
grid_encode_hash(const float* __restrict__ pts,
                 const float2* __restrict__ emb,
                 float2* __restrict__ out,
                 MetaH meta)
{
    const uint32_t tid = blockIdx.x * blockDim.x + threadIdx.x;
    if (tid >= (uint32_t)N_POINTS * N_HASH) return;

    const uint32_t n  = tid / N_HASH;       // constant div -> mulhi
    const uint32_t hl = tid - n * N_HASH;   // 0..10 -> level 5+hl

    const float inx = __ldg(pts + n * 3 + 0);
    const float iny = __ldg(pts + n * 3 + 1);
    const float inz = __ldg(pts + n * 3 + 2);

    const HashMeta m = meta.lv[hl];

    const float px = (inx + 1.0f) * 0.5f * m.scale;
    const float py = (iny + 1.0f) * 0.5f * m.scale;
    const float pz = (inz + 1.0f) * 0.5f * m.scale;

    const float gx = floorf(px), gy = floorf(py), gz = floorf(pz);
    const float fx = px - gx,   fy = py - gy,   fz = pz - gz;

    const uint32_t ix = (uint32_t)gx;
    const uint32_t iy = (uint32_t)gy;
    const uint32_t iz = (uint32_t)gz;

    const float wx[2] = {1.0f - fx, fx};
    const float wy[2] = {1.0f - fy, fy};
    const float wz[2] = {1.0f - fz, fz};

    const float2* __restrict__ table = emb + m.offset;

    const uint32_t ty0 = iy * 2654435761u;
    const uint32_t ty1 = ty0 + 2654435761u;
    const uint32_t tz0 = iz * 805459861u;
    const uint32_t tz1 = tz0 + 805459861u;

    float accx = 0.0f, accy = 0.0f;

    #pragma unroll
    for (int c = 0; c < 8; ++c) {
        const uint32_t bx = (uint32_t)(c & 1);
        const uint32_t by = (uint32_t)((c >> 1) & 1);
        const uint32_t bz = (uint32_t)(c >> 2);

        const uint32_t idx = ((ix + bx) ^ (by ? ty1 : ty0) ^ (bz ? tz1 : tz0)) & HASH_MASK;

        const float w = wx[bx] * wy[by] * wz[bz];
        const float2 f = __ldg(table + idx);
        accx = fmaf(w, f.x, accx);
        accy = fmaf(w, f.y, accy);
    }

    __stcs(out + n * (uint32_t)NUM_LEVEL + (5u + hl), make_float2(accx, accy));
}

// Host-side meta, bit-matching the reference's double-precision math.
static void compute_meta(MetaD& MD, MetaH& MH)
{
    const double ls = 1.38191288;
    const double lg = log2(ls);
    uint32_t off = 0;
    int nd = 0, nh = 0;
    for (int i = 0; i < NUM_LEVEL; ++i) {
        double s   = exp2((double)i * lg) * 16.0 - 1.0;
        int    res = (int)ceil(s) + 1;

        double   res_meta = ceil(16.0 * pow(ls, (double)i));
        double   p3 = res_meta * res_meta * res_meta;
        uint32_t p  = (p3 > 524288.0) ? 524288u : (uint32_t)p3;
        p = ((p + 7u) / 8u) * 8u;

        unsigned long long res3 =
            (unsigned long long)res * (unsigned long long)res * (unsigned long long)res;
        bool hashed = res3 > (unsigned long long)p;

        if (!hashed) {
            MD.lv[nd].scale  = (float)s;
            MD.lv[nd].res    = (uint32_t)res;
            MD.lv[nd].offset = off;
            MD.lv[nd].pad    = 0;
            nd++;
        } else {
            MH.lv[nh].scale  = (float)s;
            MH.lv[nh].offset = off;
            nh++;
        }
        off += p;
    }
}

extern "C" void kernel_launch(void* const* d_in, const int* in_sizes, int n_in,
                              void* d_out, int out_size)
{
    const float*  pts = (const float*)d_in[0];   // [N_POINTS, 3]
    const float2* emb = (const float2*)d_in[1];  // [offs[-1], 2]
    float2*       out = (float2*)d_out;          // [N_POINTS, 16] float2

    MetaD MD; MetaH MH;
    compute_meta(MD, MH);

    {
        const uint32_t total   = (uint32_t)N_POINTS * N_DENSE;
        const uint32_t blocks  = (total + 255u) / 256u;
        grid_encode_dense<<<blocks, 256>>>(pts, emb, out, MD);
    }
    {
        const uint32_t total   = (uint32_t)N_POINTS * N_HASH;
        const uint32_t blocks  = (total + 255u) / 256u;
        grid_encode_hash<<<blocks, 256>>>(pts, emb, out, MH);
    }
}

// round 15
// speedup vs baseline: 1.1371x; 1.1371x over previous
#include <cuda_runtime.h>
#include <math.h>
#include <stdint.h>

#define NUM_LEVEL 16
#define N_POINTS  262144
#define BLOCK     512           // 16 warps: warp w <-> level w
#define PTS_PER_BLK 32

struct LevelMeta {
    float    scale;
    uint32_t res;
    uint32_t offset;   // in float2 entries
    uint32_t mask;     // hsize-1 (hashed levels: hsize = 2^19)
    uint32_t hashed;
    uint32_t pad;
};

struct Meta {
    LevelMeta lv[NUM_LEVEL];
};

__global__ void __launch_bounds__(BLOCK)
grid_encode_kernel(const float* __restrict__ pts,
                   const float2* __restrict__ emb,
                   float2* __restrict__ out,
                   Meta meta)
{
    // [level][point] with pad-33 to keep both smem phases conflict-free
    __shared__ float sx[NUM_LEVEL * 33];
    __shared__ float sy[NUM_LEVEL * 33];

    const uint32_t t    = threadIdx.x;
    const uint32_t w    = t >> 5;          // warp id == level id (uniform)
    const uint32_t lane = t & 31u;
    const uint32_t pbase = blockIdx.x * PTS_PER_BLK;
    const uint32_t n    = pbase + lane;    // this lane's point

    const float inx = __ldg(pts + n * 3 + 0);
    const float iny = __ldg(pts + n * 3 + 1);
    const float inz = __ldg(pts + n * 3 + 2);

    const LevelMeta m = meta.lv[w];        // warp-uniform -> UR registers

    const float px = (inx + 1.0f) * 0.5f * m.scale;
    const float py = (iny + 1.0f) * 0.5f * m.scale;
    const float pz = (inz + 1.0f) * 0.5f * m.scale;

    const float gx = floorf(px), gy = floorf(py), gz = floorf(pz);
    const float fx = px - gx,   fy = py - gy,   fz = pz - gz;

    const uint32_t ix = (uint32_t)gx;
    const uint32_t iy = (uint32_t)gy;
    const uint32_t iz = (uint32_t)gz;

    const float wx[2] = {1.0f - fx, fx};
    const float wy[2] = {1.0f - fy, fy};
    const float wz[2] = {1.0f - fz, fz};

    const float2* __restrict__ table = emb + m.offset;

    float accx = 0.0f, accy = 0.0f;

    if (m.hashed) {    // warp-uniform branch: zero divergence
        const uint32_t mask = m.mask;
        const uint32_t ty0 = iy * 2654435761u;
        const uint32_t ty1 = ty0 + 2654435761u;
        const uint32_t tz0 = iz * 805459861u;
        const uint32_t tz1 = tz0 + 805459861u;

        #pragma unroll
        for (int c = 0; c < 8; ++c) {
            const uint32_t bx = (uint32_t)(c & 1);
            const uint32_t by = (uint32_t)((c >> 1) & 1);
            const uint32_t bz = (uint32_t)(c >> 2);
            const uint32_t idx = ((ix + bx) ^ (by ? ty1 : ty0) ^ (bz ? tz1 : tz0)) & mask;

            const float wgt = wx[bx] * wy[by] * wz[bz];
            const float2 f = __ldg(table + idx);
            accx = fmaf(wgt, f.x, accx);
            accy = fmaf(wgt, f.y, accy);
        }
    } else {
        const uint32_t r  = m.res;
        const uint32_t r2 = r * r;
        const uint32_t base = ix + iy * r + iz * r2;

        #pragma unroll
        for (int c = 0; c < 8; ++c) {
            const uint32_t bx = (uint32_t)(c & 1);
            const uint32_t by = (uint32_t)((c >> 1) & 1);
            const uint32_t bz = (uint32_t)(c >> 2);
            const uint32_t idx = base + bx + by * r + bz * r2;

            const float wgt = wx[bx] * wy[by] * wz[bz];
            const float2 f = __ldg(table + idx);
            accx = fmaf(wgt, f.x, accx);
            accy = fmaf(wgt, f.y, accy);
        }
    }

    // Transpose through smem: write [level][point] (stride-1 in lane: no conflicts)
    sx[w * 33 + lane] = accx;
    sy[w * 33 + lane] = accy;
    __syncthreads();

    // Coalesced store: 512 contiguous float2 per block.
    // thread t -> global float2 index pbase*16 + t ; p = t>>4, l = t&15
    const uint32_t p = t >> 4;
    const uint32_t l = t & 15u;
    const float ox = sx[l * 33 + p];   // lane stride 33 words: conflict-free
    const float oy = sy[l * 33 + p];
    __stcs(out + pbase * (uint32_t)NUM_LEVEL + t, make_float2(ox, oy));
}

// Host-side meta, bit-matching the reference's double-precision math.
static void compute_meta(Meta& M)
{
    const double ls = 1.38191288;
    const double lg = log2(ls);
    uint32_t off = 0;
    for (int i = 0; i < NUM_LEVEL; ++i) {
        double s   = exp2((double)i * lg) * 16.0 - 1.0;
        int    res = (int)ceil(s) + 1;

        double   res_meta = ceil(16.0 * pow(ls, (double)i));
        double   p3 = res_meta * res_meta * res_meta;
        uint32_t p  = (p3 > 524288.0) ? 524288u : (uint32_t)p3;
        p = ((p + 7u) / 8u) * 8u;

        unsigned long long res3 =
            (unsigned long long)res * (unsigned long long)res * (unsigned long long)res;
        bool hashed = res3 > (unsigned long long)p;

        M.lv[i].scale  = (float)s;
        M.lv[i].res    = (uint32_t)res;
        M.lv[i].offset = off;
        M.lv[i].mask   = p - 1u;
        M.lv[i].hashed = hashed ? 1u : 0u;
        M.lv[i].pad    = 0;

        off += p;
    }
}

extern "C" void kernel_launch(void* const* d_in, const int* in_sizes, int n_in,
                              void* d_out, int out_size)
{
    const float*  pts = (const float*)d_in[0];   // [N_POINTS, 3]
    const float2* emb = (const float2*)d_in[1];  // [offs[-1], 2]
    float2*       out = (float2*)d_out;          // [N_POINTS, 16] float2

    Meta M;
    compute_meta(M);

    const uint32_t blocks = N_POINTS / PTS_PER_BLK;   // 8192, exact

    grid_encode_kernel<<<blocks, BLOCK>>>(pts, emb, out, M);
}

// round 16
// speedup vs baseline: 1.1662x; 1.0256x over previous
#include <cuda_runtime.h>
#include <math.h>
#include <stdint.h>

#define NUM_LEVEL 16
#define N_POINTS  262144
#define BLOCK     512           // 16 warps: warp w <-> level w
#define PTS_PER_BLK 32

struct LevelMeta {
    float    scale;
    uint32_t res;
    uint32_t offset;   // in float2 entries (multiple of 8 -> float4-aligned)
    uint32_t mask;     // hsize-1 (hashed levels: hsize = 2^19)
    uint32_t hashed;
    uint32_t pad;
};

struct Meta {
    LevelMeta lv[NUM_LEVEL];
};

__global__ void __launch_bounds__(BLOCK)
grid_encode_kernel(const float* __restrict__ pts,
                   const float2* __restrict__ emb,
                   float2* __restrict__ out,
                   Meta meta)
{
    __shared__ float sx[NUM_LEVEL * 33];
    __shared__ float sy[NUM_LEVEL * 33];

    const uint32_t t    = threadIdx.x;
    const uint32_t w    = t >> 5;          // warp id == level id (uniform)
    const uint32_t lane = t & 31u;
    const uint32_t pbase = blockIdx.x * PTS_PER_BLK;
    const uint32_t n    = pbase + lane;    // this lane's point

    const float inx = __ldg(pts + n * 3 + 0);
    const float iny = __ldg(pts + n * 3 + 1);
    const float inz = __ldg(pts + n * 3 + 2);

    const LevelMeta m = meta.lv[w];        // warp-uniform -> UR registers

    const float px = (inx + 1.0f) * 0.5f * m.scale;
    const float py = (iny + 1.0f) * 0.5f * m.scale;
    const float pz = (inz + 1.0f) * 0.5f * m.scale;

    const float gx = floorf(px), gy = floorf(py), gz = floorf(pz);
    const float fx = px - gx,   fy = py - gy,   fz = pz - gz;

    const uint32_t ix = (uint32_t)gx;
    const uint32_t iy = (uint32_t)gy;
    const uint32_t iz = (uint32_t)gz;

    const float wx0 = 1.0f - fx, wx1 = fx;
    const float wy[2] = {1.0f - fy, fy};
    const float wz[2] = {1.0f - fz, fz};

    const float2* __restrict__ table = emb + m.offset;

    float accx = 0.0f, accy = 0.0f;

    if (m.hashed) {    // warp-uniform branch
        // x-prime = 1, hsize = 2^19: for EVEN ix, corners (ix, ix+1) land at
        // idxA and idxA^1 -> one aligned float4. Odd-ix lanes fetch corner B
        // with a predicated LDG.64 (~half the lanes active).
        const float4* __restrict__ tab4 = (const float4*)table;
        const uint32_t mask  = m.mask;
        const bool     ixeven = (ix & 1u) == 0u;
        const uint32_t ty0 = iy * 2654435761u;
        const uint32_t ty1 = ty0 + 2654435761u;
        const uint32_t tz0 = iz * 805459861u;
        const uint32_t tz1 = tz0 + 805459861u;

        #pragma unroll
        for (int p = 0; p < 4; ++p) {
            const uint32_t by = (uint32_t)(p & 1);
            const uint32_t bz = (uint32_t)(p >> 1);
            const uint32_t tt = (by ? ty1 : ty0) ^ (bz ? tz1 : tz0);

            const uint32_t idxA = (ix ^ tt) & mask;      // corner bx=0
            const bool     odd  = (idxA & 1u) != 0u;

            const float4 f4 = __ldg(tab4 + (idxA >> 1)); // always covers corner A

            const float2 cA = odd ? make_float2(f4.z, f4.w)
                                  : make_float2(f4.x, f4.y);
            float2 cB;
            if (ixeven) {
                cB = odd ? make_float2(f4.x, f4.y)
                         : make_float2(f4.z, f4.w);
            } else {
                cB = __ldg(table + (((ix + 1u) ^ tt) & mask));
            }

            const float wyz = wy[by] * wz[bz];
            const float wA  = wx0 * wyz;
            const float wB  = wx1 * wyz;

            accx = fmaf(wA, cA.x, accx);
            accy = fmaf(wA, cA.y, accy);
            accx = fmaf(wB, cB.x, accx);
            accy = fmaf(wB, cB.y, accy);
        }
    } else {
        const uint32_t r  = m.res;
        const uint32_t r2 = r * r;
        const uint32_t base = ix + iy * r + iz * r2;
        const float wxp[2] = {wx0, wx1};

        #pragma unroll
        for (int c = 0; c < 8; ++c) {
            const uint32_t bx = (uint32_t)(c & 1);
            const uint32_t by = (uint32_t)((c >> 1) & 1);
            const uint32_t bz = (uint32_t)(c >> 2);
            const uint32_t idx = base + bx + by * r + bz * r2;

            const float wgt = wxp[bx] * wy[by] * wz[bz];
            const float2 f = __ldg(table + idx);
            accx = fmaf(wgt, f.x, accx);
            accy = fmaf(wgt, f.y, accy);
        }
    }

    // Transpose through smem -> fully coalesced block store
    sx[w * 33 + lane] = accx;
    sy[w * 33 + lane] = accy;
    __syncthreads();

    const uint32_t p = t >> 4;
    const uint32_t l = t & 15u;
    const float ox = sx[l * 33 + p];
    const float oy = sy[l * 33 + p];
    __stcs(out + pbase * (uint32_t)NUM_LEVEL + t, make_float2(ox, oy));
}

// Host-side meta, bit-matching the reference's double-precision math.
static void compute_meta(Meta& M)
{
    const double ls = 1.38191288;
    const double lg = log2(ls);
    uint32_t off = 0;
    for (int i = 0; i < NUM_LEVEL; ++i) {
        double s   = exp2((double)i * lg) * 16.0 - 1.0;
        int    res = (int)ceil(s) + 1;

        double   res_meta = ceil(16.0 * pow(ls, (double)i));
        double   p3 = res_meta * res_meta * res_meta;
        uint32_t p  = (p3 > 524288.0) ? 524288u : (uint32_t)p3;
        p = ((p + 7u) / 8u) * 8u;

        unsigned long long res3 =
            (unsigned long long)res * (unsigned long long)res * (unsigned long long)res;
        bool hashed = res3 > (unsigned long long)p;

        M.lv[i].scale  = (float)s;
        M.lv[i].res    = (uint32_t)res;
        M.lv[i].offset = off;
        M.lv[i].mask   = p - 1u;
        M.lv[i].hashed = hashed ? 1u : 0u;
        M.lv[i].pad    = 0;

        off += p;
    }
}

extern "C" void kernel_launch(void* const* d_in, const int* in_sizes, int n_in,
                              void* d_out, int out_size)
{
    const float*  pts = (const float*)d_in[0];   // [N_POINTS, 3]
    const float2* emb = (const float2*)d_in[1];  // [offs[-1], 2]
    float2*       out = (float2*)d_out;          // [N_POINTS, 16] float2

    Meta M;
    compute_meta(M);

    const uint32_t blocks = N_POINTS / PTS_PER_BLK;   // 8192, exact

    grid_encode_kernel<<<blocks, BLOCK>>>(pts, emb, out, M);
}

// round 17
// speedup vs baseline: 1.1703x; 1.0035x over previous
#include <cuda_runtime.h>
#include <math.h>
#include <stdint.h>

#define NUM_LEVEL 16
#define N_POINTS  262144
#define BLOCK     512           // 16 warps: warp w <-> level w
#define PTS_PER_BLK 32

struct LevelMeta {
    float    scale;
    uint32_t res;
    uint32_t offset;   // in float2 entries (multiple of 8 -> float4-aligned)
    uint32_t mask;     // hsize-1 (hashed levels: hsize = 2^19)
    uint32_t hashed;
    uint32_t pad;
};

struct Meta {
    LevelMeta lv[NUM_LEVEL];
};

__global__ void __launch_bounds__(BLOCK)
grid_encode_kernel(const float* __restrict__ pts,
                   const float2* __restrict__ emb,
                   float2* __restrict__ out,
                   Meta meta)
{
    __shared__ float sx[NUM_LEVEL * 33];
    __shared__ float sy[NUM_LEVEL * 33];

    const uint32_t t    = threadIdx.x;
    const uint32_t w    = t >> 5;          // warp id == level id (uniform)
    const uint32_t lane = t & 31u;
    const uint32_t pbase = blockIdx.x * PTS_PER_BLK;
    const uint32_t n    = pbase + lane;    // this lane's point

    const float inx = __ldg(pts + n * 3 + 0);
    const float iny = __ldg(pts + n * 3 + 1);
    const float inz = __ldg(pts + n * 3 + 2);

    const LevelMeta m = meta.lv[w];        // warp-uniform -> UR registers

    const float px = (inx + 1.0f) * 0.5f * m.scale;
    const float py = (iny + 1.0f) * 0.5f * m.scale;
    const float pz = (inz + 1.0f) * 0.5f * m.scale;

    const float gx = floorf(px), gy = floorf(py), gz = floorf(pz);
    const float fx = px - gx,   fy = py - gy,   fz = pz - gz;

    const uint32_t ix = (uint32_t)gx;
    const uint32_t iy = (uint32_t)gy;
    const uint32_t iz = (uint32_t)gz;

    const float wx0 = 1.0f - fx, wx1 = fx;
    const float wy[2] = {1.0f - fy, fy};
    const float wz[2] = {1.0f - fz, fz};

    const float2* __restrict__ table = emb + m.offset;
    const float4* __restrict__ tab4  = (const float4*)table;

    float accx = 0.0f, accy = 0.0f;

    if (m.hashed) {    // warp-uniform branch
        // x-prime = 1, hsize = 2^19: for EVEN ix, corners (ix, ix+1) land at
        // idxA and idxA^1 -> one aligned float4. Odd-ix lanes fetch corner B
        // with a predicated LDG.64 (~half the lanes active).
        const uint32_t mask  = m.mask;
        const bool     ixeven = (ix & 1u) == 0u;
        const uint32_t ty0 = iy * 2654435761u;
        const uint32_t ty1 = ty0 + 2654435761u;
        const uint32_t tz0 = iz * 805459861u;
        const uint32_t tz1 = tz0 + 805459861u;

        #pragma unroll
        for (int p = 0; p < 4; ++p) {
            const uint32_t by = (uint32_t)(p & 1);
            const uint32_t bz = (uint32_t)(p >> 1);
            const uint32_t tt = (by ? ty1 : ty0) ^ (bz ? tz1 : tz0);

            const uint32_t idxA = (ix ^ tt) & mask;      // corner bx=0
            const bool     odd  = (idxA & 1u) != 0u;

            const float4 f4 = __ldg(tab4 + (idxA >> 1)); // always covers corner A

            const float2 cA = odd ? make_float2(f4.z, f4.w)
                                  : make_float2(f4.x, f4.y);
            float2 cB;
            if (ixeven) {
                cB = odd ? make_float2(f4.x, f4.y)
                         : make_float2(f4.z, f4.w);
            } else {
                cB = __ldg(table + (((ix + 1u) ^ tt) & mask));
            }

            const float wyz = wy[by] * wz[bz];
            const float wA  = wx0 * wyz;
            const float wB  = wx1 * wyz;

            accx = fmaf(wA, cA.x, accx);
            accy = fmaf(wA, cA.y, accy);
            accx = fmaf(wB, cB.x, accx);
            accy = fmaf(wB, cB.y, accy);
        }
    } else {
        // Dense warp: same x-pair trick. Corner pair is (idxA, idxA+1);
        // when idxA is even both live in the aligned float4 at idxA>>1.
        // The float4 read never leaves the table: span is [idxA&~1, idxA|1],
        // bounded by res^3-1 < hsize (offset is 8-entry aligned).
        const uint32_t r  = m.res;
        const uint32_t r2 = r * r;
        const uint32_t base = ix + iy * r + iz * r2;

        #pragma unroll
        for (int p = 0; p < 4; ++p) {
            const uint32_t by = (uint32_t)(p & 1);
            const uint32_t bz = (uint32_t)(p >> 1);
            const uint32_t idxA = base + by * r + bz * r2;   // corner bx=0
            const bool     odd  = (idxA & 1u) != 0u;

            const float4 f4 = __ldg(tab4 + (idxA >> 1));

            const float2 cA = odd ? make_float2(f4.z, f4.w)
                                  : make_float2(f4.x, f4.y);
            float2 cB;
            if (!odd) {                    // idxA even: idxA+1 in same float4
                cB = make_float2(f4.z, f4.w);
            } else {                       // idxA odd: separate LDG.64
                cB = __ldg(table + idxA + 1u);
            }

            const float wyz = wy[by] * wz[bz];
            const float wA  = wx0 * wyz;
            const float wB  = wx1 * wyz;

            accx = fmaf(wA, cA.x, accx);
            accy = fmaf(wA, cA.y, accy);
            accx = fmaf(wB, cB.x, accx);
            accy = fmaf(wB, cB.y, accy);
        }
    }

    // Transpose through smem -> fully coalesced block store
    sx[w * 33 + lane] = accx;
    sy[w * 33 + lane] = accy;
    __syncthreads();

    const uint32_t p = t >> 4;
    const uint32_t l = t & 15u;
    const float ox = sx[l * 33 + p];
    const float oy = sy[l * 33 + p];
    __stcs(out + pbase * (uint32_t)NUM_LEVEL + t, make_float2(ox, oy));
}

// Host-side meta, bit-matching the reference's double-precision math.
static void compute_meta(Meta& M)
{
    const double ls = 1.38191288;
    const double lg = log2(ls);
    uint32_t off = 0;
    for (int i = 0; i < NUM_LEVEL; ++i) {
        double s   = exp2((double)i * lg) * 16.0 - 1.0;
        int    res = (int)ceil(s) + 1;

        double   res_meta = ceil(16.0 * pow(ls, (double)i));
        double   p3 = res_meta * res_meta * res_meta;
        uint32_t p  = (p3 > 524288.0) ? 524288u : (uint32_t)p3;
        p = ((p + 7u) / 8u) * 8u;

        unsigned long long res3 =
            (unsigned long long)res * (unsigned long long)res * (unsigned long long)res;
        bool hashed = res3 > (unsigned long long)p;

        M.lv[i].scale  = (float)s;
        M.lv[i].res    = (uint32_t)res;
        M.lv[i].offset = off;
        M.lv[i].mask   = p - 1u;
        M.lv[i].hashed = hashed ? 1u : 0u;
        M.lv[i].pad    = 0;

        off += p;
    }
}

extern "C" void kernel_launch(void* const* d_in, const int* in_sizes, int n_in,
                              void* d_out, int out_size)
{
    const float*  pts = (const float*)d_in[0];   // [N_POINTS, 3]
    const float2* emb = (const float2*)d_in[1];  // [offs[-1], 2]
    float2*       out = (float2*)d_out;          // [N_POINTS, 16] float2

    Meta M;
    compute_meta(M);

    const uint32_t blocks = N_POINTS / PTS_PER_BLK;   // 8192, exact

    grid_encode_kernel<<<blocks, BLOCK>>>(pts, emb, out, M);
}